// round 16
// baseline (speedup 1.0000x reference)
#include <cuda_runtime.h>
#include <cuda_bf16.h>
#include <cstdint>
#include <cstddef>

#define BATCH 4
#define CDIM  512
#define KDIM  64
#define NDIM  4096
#define NN    ((size_t)NDIM * NDIM)

// ---------------- device scratch (no allocs allowed) ----------------
// f/g operand arrays are stored PRE-SWIZZLED (XOR-16B within each
// 128-row x 64-col tile; pattern depends only on row&7) so attention can
// bulk-copy them linearly.  f is additionally pre-scaled by log2(e).
// d_w_* are stored pre-swizzled in CHUNK-MAJOR tile order: chunk c (k-range
// 64c..64c+63) occupies elements [c*8192, (c+1)*8192) as a [128m][64k]
// XOR-swizzled tile, so fg can bulk-copy 16KB per chunk linearly.
__device__ __align__(128) __nv_bfloat16 d_fa_hi[BATCH * NDIM * KDIM]; // f, i-major
__device__ __align__(128) __nv_bfloat16 d_fa_lo[BATCH * NDIM * KDIM];
__device__ __align__(128) __nv_bfloat16 d_gb_hi[BATCH * NDIM * KDIM]; // g, j-major
__device__ __align__(128) __nv_bfloat16 d_gb_lo[BATCH * NDIM * KDIM];
__device__ __align__(128) __nv_bfloat16 d_w_hi[128 * CDIM];           // [Wq*L2E;Wk] split
__device__ __align__(128) __nv_bfloat16 d_w_lo[128 * CDIM];
__device__ float d_Z[BATCH * NDIM];       // column sums of 2^s'
__device__ float d_rowsum[BATCH * NDIM];  // row sums of beta
__device__ float d_y[BATCH * CDIM];
__device__ float d_xbar[BATCH * CDIM];

// 2^x  (operands pre-scaled by log2 e upstream)
__device__ __forceinline__ float fast_exp2(float x) {
    float y;
    asm("ex2.approx.ftz.f32 %0, %1;" : "=f"(y) : "f"(x));
    return y;
}

__device__ __forceinline__ float warp_sum(float v) {
    #pragma unroll
    for (int o = 16; o; o >>= 1) v += __shfl_xor_sync(0xFFFFFFFFu, v, o);
    return v;
}

__device__ __forceinline__ uint32_t smem_u32(const void* p) {
    uint32_t a;
    asm("{ .reg .u64 t; cvta.to.shared.u64 t, %1; cvt.u32.u64 %0, t; }"
        : "=r"(a) : "l"(p));
    return a;
}

// hi bf16x2 of (v0,v1) by mantissa truncation (exact bf16 bits)
__device__ __forceinline__ uint32_t pack_hi2(float v0, float v1) {
    uint32_t r;
    asm("prmt.b32 %0, %1, %2, 0x7632;"
        : "=r"(r) : "r"(__float_as_uint(v0)), "r"(__float_as_uint(v1)));
    return r;
}
// residual lo bf16x2: lo_k = v_k - trunc_bf16(v_k), rounded to bf16
__device__ __forceinline__ uint32_t pack_lo2(float v0, float v1) {
    float l0 = v0 - __uint_as_float(__float_as_uint(v0) & 0xFFFF0000u);
    float l1 = v1 - __uint_as_float(__float_as_uint(v1) & 0xFFFF0000u);
    uint32_t r;
    asm("cvt.rn.bf16x2.f32 %0, %1, %2;" : "=r"(r) : "f"(l1), "f"(l0));
    return r;
}

// A fragment (m16 x k16) via ldmatrix x4 from m-major SW-swizzled [rows][64] bf16 tile
__device__ __forceinline__ void ldA(uint32_t tile, int rbase, int kc, int lane, uint32_t* a) {
    int r = rbase + (lane & 15);
    int c = kc + (lane >> 4);
    uint32_t addr = tile + r * 128 + ((c ^ (r & 7)) << 4);
    asm volatile("ldmatrix.sync.aligned.m8n8.x4.shared.b16 {%0,%1,%2,%3}, [%4];"
                 : "=r"(a[0]), "=r"(a[1]), "=r"(a[2]), "=r"(a[3]) : "r"(addr));
}

// TWO B fragments (two adjacent n8 x k16) via one ldmatrix x4
__device__ __forceinline__ void ldB4(uint32_t tile, int rbase, int kc, int lane, uint32_t* b01) {
    int r = rbase + ((lane >> 1) & 8) + (lane & 7);
    int c = kc + ((lane >> 3) & 1);
    uint32_t addr = tile + r * 128 + ((c ^ (r & 7)) << 4);
    asm volatile("ldmatrix.sync.aligned.m8n8.x4.shared.b16 {%0,%1,%2,%3}, [%4];"
                 : "=r"(b01[0]), "=r"(b01[1]), "=r"(b01[2]), "=r"(b01[3]) : "r"(addr));
}

__device__ __forceinline__ void mma_bf16(float* acc, const uint32_t* a, const uint32_t* bb) {
    asm volatile(
        "mma.sync.aligned.m16n8k16.row.col.f32.bf16.bf16.f32 "
        "{%0,%1,%2,%3}, {%4,%5,%6,%7}, {%8,%9}, {%0,%1,%2,%3};"
        : "+f"(acc[0]), "+f"(acc[1]), "+f"(acc[2]), "+f"(acc[3])
        : "r"(a[0]), "r"(a[1]), "r"(a[2]), "r"(a[3]), "r"(bb[0]), "r"(bb[1]));
}

// ---------------- mbarrier + bulk-copy helpers (sm_90 baseline PTX) ----------------
#define MBARRIER_INIT(mbar, count) \
    asm volatile("mbarrier.init.shared.b64 [%0], %1;" \
                 :: "r"((uint32_t)(mbar)), "r"((uint32_t)(count)) : "memory")
#define MBARRIER_EXPECT_TX(mbar, bytes) \
    asm volatile("mbarrier.arrive.expect_tx.shared.b64 _, [%0], %1;" \
                 :: "r"((uint32_t)(mbar)), "r"((uint32_t)(bytes)) : "memory")
#define FENCE_PROXY_ASYNC() \
    asm volatile("fence.proxy.async.shared::cta;" ::: "memory")
#define CP_BULK(dst_smem, src_gmem, bytes, mbar) \
    asm volatile("cp.async.bulk.shared::cta.global.mbarrier::complete_tx::bytes " \
                 "[%0], [%1], %2, [%3];" \
                 :: "r"((uint32_t)(dst_smem)), "l"(src_gmem), "r"((uint32_t)(bytes)), \
                    "r"((uint32_t)(mbar)) : "memory")

__device__ __forceinline__ void mbar_wait_parity(uint32_t mbar, uint32_t parity) {
    uint32_t done;
    asm volatile(
        "{\n\t.reg .pred p;\n\t"
        "mbarrier.try_wait.parity.acquire.cta.shared::cta.b64 p, [%1], %2;\n\t"
        "selp.b32 %0, 1, 0, p;\n\t}"
        : "=r"(done) : "r"(mbar), "r"(parity) : "memory");
    if (!done) {
        asm volatile(
            "{\n\t.reg .pred P1;\n\t"
            "WAIT_LOOP_%=:\n\t"
            "mbarrier.try_wait.parity.acquire.cta.shared::cta.b64 P1, [%0], %1, 0x989680;\n\t"
            "@P1 bra.uni WAIT_DONE_%=;\n\t"
            "bra.uni WAIT_LOOP_%=;\n\t"
            "WAIT_DONE_%=:\n\t}"
            :: "r"(mbar), "r"(parity) : "memory");
    }
}

// ---------------- W split prep + Z/rowsum zero ----------------
// Wq rows pre-scaled by log2(e).  Output PRE-SWIZZLED, CHUNK-MAJOR (see above).
__global__ __launch_bounds__(256) void wsplit_kernel(const float* __restrict__ Wq,
                                                     const float* __restrict__ Wk) {
    int idx = blockIdx.x * blockDim.x + threadIdx.x;
    if (idx < BATCH * NDIM) { d_rowsum[idx] = 0.f; d_Z[idx] = 0.f; }
    if (idx >= 128 * CDIM) return;
    int m = idx >> 9;
    int c = idx & 511;
    float w = (m < 64) ? Wq[m * CDIM + c] * 1.4426950408889634f
                       : Wk[(m - 64) * CDIM + c];
    __nv_bfloat16 hi = __float2bfloat16(w);
    int chunk = c >> 6, kin = c & 63, oct = kin >> 3, e = kin & 7;
    int off = chunk * 8192 + m * 64 + ((oct ^ (m & 7)) << 3) + e;
    d_w_hi[off] = hi;
    d_w_lo[off] = __float2bfloat16(w - __bfloat162float(hi));
}

// ---------------- FG: [f;g] = [Wq*L2E;Wk] @ x[b] via bf16x3 mma.sync ----------------
// Tile: [128 m] x [64 n=i], K=512 in 8 chunks of 64.  grid (64, BATCH), 2 CTAs/SM.
// W chunks stream via 2-stage cp.async.bulk ring (pre-swizzled chunk tiles);
// x chunk prefetched into registers during the previous chunk's MMA.
// SMEM: W ring 2 x 32K @0; sXhi @65536 8K; sXlo @73728 8K; mbars @81920.
#define FG_SMEM 82048

__global__ __launch_bounds__(256, 2) void fg_kernel(const float* __restrict__ x) {
    extern __shared__ __align__(1024) char dynsm[];
    uint32_t smem_base = smem_u32(dynsm);
    uint4* sXhi = (uint4*)(dynsm + 65536);
    uint4* sXlo = (uint4*)(dynsm + 73728);
    float* S = (float*)dynsm;  // [128][68] alias after mainloop
    const uint32_t MBF0 = smem_base + 81920;
    const uint32_t MBF1 = smem_base + 81928;
    const char* wh = (const char*)d_w_hi;
    const char* wl = (const char*)d_w_lo;

    int b = blockIdx.y;
    int i0 = blockIdx.x * 64;
    int tid = threadIdx.x;
    int lane = tid & 31, wid = tid >> 5;
    int wm = wid >> 1, wn = wid & 1;
    const float* xb = x + (size_t)b * CDIM * NDIM;

    int xn[2], xoct[2];
    #pragma unroll
    for (int t = 0; t < 2; t++) {
        int idx = tid + t * 256;
        xn[t] = idx & 63;
        xoct[t] = idx >> 6;
    }

    float acc[2][4][4];
    #pragma unroll
    for (int mf = 0; mf < 2; mf++)
        #pragma unroll
        for (int nf = 0; nf < 4; nf++)
            #pragma unroll
            for (int e = 0; e < 4; e++) acc[mf][nf][e] = 0.f;

    // prologue: init ring, kick off W chunk 0, prefetch x chunk 0 regs
    if (tid == 0) {
        MBARRIER_INIT(MBF0, 1);
        MBARRIER_INIT(MBF1, 1);
        FENCE_PROXY_ASYNC();
        MBARRIER_EXPECT_TX(MBF0, 32768);
        CP_BULK(smem_base,         wh, 16384, MBF0);
        CP_BULK(smem_base + 16384, wl, 16384, MBF0);
    }
    float vreg[2][8];
    #pragma unroll
    for (int t = 0; t < 2; t++) {
        const float* src = xb + (size_t)(xoct[t] * 8) * NDIM + i0 + xn[t];
        #pragma unroll
        for (int j = 0; j < 8; j++) vreg[t][j] = src[(size_t)j * NDIM];
    }
    __syncthreads();  // mbar init visible before any wait

    for (int it = 0; it < 8; it++) {
        // barrier: prev iteration's MMA done with sX and with stage ((it+1)&1)
        __syncthreads();

        // issue W copy for chunk it+1 into stage (it+1)&1 (freed by chunk it-1)
        if (tid == 0 && it + 1 < 8) {
            int ns = (it + 1) & 1;
            uint32_t mb = ns ? MBF1 : MBF0;
            uint32_t st = smem_base + ns * 32768;
            MBARRIER_EXPECT_TX(mb, 32768);
            CP_BULK(st,         wh + (size_t)(it + 1) * 16384, 16384, mb);
            CP_BULK(st + 16384, wl + (size_t)(it + 1) * 16384, 16384, mb);
        }

        // store prefetched x regs -> smem (convert to split bf16)
        #pragma unroll
        for (int t = 0; t < 2; t++) {
            uint4 hw, lw;
            hw.x = pack_hi2(vreg[t][0], vreg[t][1]); lw.x = pack_lo2(vreg[t][0], vreg[t][1]);
            hw.y = pack_hi2(vreg[t][2], vreg[t][3]); lw.y = pack_lo2(vreg[t][2], vreg[t][3]);
            hw.z = pack_hi2(vreg[t][4], vreg[t][5]); lw.z = pack_lo2(vreg[t][4], vreg[t][5]);
            hw.w = pack_hi2(vreg[t][6], vreg[t][7]); lw.w = pack_lo2(vreg[t][6], vreg[t][7]);
            int soff = xn[t] * 8 + (xoct[t] ^ (xn[t] & 7));
            sXhi[soff] = hw;
            sXlo[soff] = lw;
        }
        __syncthreads();  // sX visible to all warps

        // prefetch next x chunk; latency hides under the MMA loop
        if (it < 7) {
            #pragma unroll
            for (int t = 0; t < 2; t++) {
                const float* src = xb + (size_t)((it + 1) * 64 + xoct[t] * 8) * NDIM
                                   + i0 + xn[t];
                #pragma unroll
                for (int j = 0; j < 8; j++) vreg[t][j] = src[(size_t)j * NDIM];
            }
        }

        // wait for this chunk's W tiles
        int s = it & 1;
        mbar_wait_parity(s ? MBF1 : MBF0, (it >> 1) & 1);

        uint32_t tA = smem_base + s * 32768, tAlo = tA + 16384;
        uint32_t tB = smem_base + 65536, tBlo = smem_base + 73728;
        #pragma unroll
        for (int ks = 0; ks < 4; ks++) {
            int kc = ks * 2;
            uint32_t ahi[2][4], alo[2][4], bhi[4][2], blo[4][2];
            #pragma unroll
            for (int mf = 0; mf < 2; mf++) ldA(tA, wm * 32 + mf * 16, kc, lane, ahi[mf]);
            ldB4(tB, wn * 32,      kc, lane, &bhi[0][0]);
            ldB4(tB, wn * 32 + 16, kc, lane, &bhi[2][0]);
            #pragma unroll
            for (int mf = 0; mf < 2; mf++)
                #pragma unroll
                for (int nf = 0; nf < 4; nf++) mma_bf16(acc[mf][nf], ahi[mf], bhi[nf]);
            #pragma unroll
            for (int mf = 0; mf < 2; mf++) ldA(tAlo, wm * 32 + mf * 16, kc, lane, alo[mf]);
            #pragma unroll
            for (int mf = 0; mf < 2; mf++)
                #pragma unroll
                for (int nf = 0; nf < 4; nf++) mma_bf16(acc[mf][nf], alo[mf], bhi[nf]);
            ldB4(tBlo, wn * 32,      kc, lane, &blo[0][0]);
            ldB4(tBlo, wn * 32 + 16, kc, lane, &blo[2][0]);
            #pragma unroll
            for (int mf = 0; mf < 2; mf++)
                #pragma unroll
                for (int nf = 0; nf < 4; nf++) mma_bf16(acc[mf][nf], ahi[mf], blo[nf]);
        }
    }
    __syncthreads();

    // stage fp32 S[m][i] (128 x 64, stride 68)
    #pragma unroll
    for (int mf = 0; mf < 2; mf++)
        #pragma unroll
        for (int nf = 0; nf < 4; nf++) {
            int r = wm * 32 + mf * 16 + (lane >> 2);
            int cc = wn * 32 + nf * 8 + (lane & 3) * 2;
            S[r * 68 + cc]           = acc[mf][nf][0];
            S[r * 68 + cc + 1]       = acc[mf][nf][1];
            S[(r + 8) * 68 + cc]     = acc[mf][nf][2];
            S[(r + 8) * 68 + cc + 1] = acc[mf][nf][3];
        }
    __syncthreads();

    // write split bf16 PRE-SWIZZLED: chunk index XORed with (row & 7)
    int arr = lane >> 3, chunk = lane & 7;
    int mbase = (arr >= 2 ? 64 : 0) + chunk * 8;
    __nv_bfloat16* dst = (arr == 0) ? d_fa_hi : (arr == 1) ? d_fa_lo
                       : (arr == 2) ? d_gb_hi : d_gb_lo;
    bool lo_arr = (arr & 1);
    for (int r = wid; r < 64; r += 8) {
        uint4 wv;
        float v0, v1;
        v0 = S[(mbase + 0) * 68 + r]; v1 = S[(mbase + 1) * 68 + r];
        wv.x = lo_arr ? pack_lo2(v0, v1) : pack_hi2(v0, v1);
        v0 = S[(mbase + 2) * 68 + r]; v1 = S[(mbase + 3) * 68 + r];
        wv.y = lo_arr ? pack_lo2(v0, v1) : pack_hi2(v0, v1);
        v0 = S[(mbase + 4) * 68 + r]; v1 = S[(mbase + 5) * 68 + r];
        wv.z = lo_arr ? pack_lo2(v0, v1) : pack_hi2(v0, v1);
        v0 = S[(mbase + 6) * 68 + r]; v1 = S[(mbase + 7) * 68 + r];
        wv.w = lo_arr ? pack_lo2(v0, v1) : pack_hi2(v0, v1);
        int chs = chunk ^ (r & 7);
        *(uint4*)(dst + ((size_t)b * NDIM + i0 + r) * KDIM + chs * 8) = wv;
    }
}

// ---------------- attention passes (split, fine-grained grids) ----------------
// grid (32,32,BATCH) = (jtile, itile, b); tile 128(i) x 128(j); 256 threads.
// Operands loaded via 4 bulk copies (arrays pre-swizzled).  Register epilogues.
// PASS 1: Z[b,j] += sum_i 2^s.  PASS 2: beta = 2^s/Z via paired STG.128
// (lane l<->l^1 exchange makes each store a full float4), rowsum += sum_j beta.
// SMEM: [0,64K) 4 operand tiles; sZ @65536 (512B); mbar @66048.
#define ATTN_SMEM 66176

template <int PASS>
__global__ __launch_bounds__(256, 2) void attn_kernel(float* __restrict__ beta_out) {
    extern __shared__ __align__(1024) char dynsm[];
    uint32_t smem_base = smem_u32(dynsm);
    float* sZ = (float*)(dynsm + 65536);
    const uint32_t MB = smem_base + 66048;

    int b  = blockIdx.z;
    int i0 = blockIdx.y * 128;
    int j0 = blockIdx.x * 128;
    int tid = threadIdx.x;
    int lane = tid & 31, wid = tid >> 5;
    int wm = wid >> 2, wn = wid & 3;

    if (tid == 0) {
        MBARRIER_INIT(MB, 1);
        FENCE_PROXY_ASYNC();
        MBARRIER_EXPECT_TX(MB, 65536);
        CP_BULK(smem_base,         (const char*)(d_fa_hi + ((size_t)b * NDIM + i0) * KDIM),
                16384, MB);
        CP_BULK(smem_base + 16384, (const char*)(d_fa_lo + ((size_t)b * NDIM + i0) * KDIM),
                16384, MB);
        CP_BULK(smem_base + 32768, (const char*)(d_gb_hi + ((size_t)b * NDIM + j0) * KDIM),
                16384, MB);
        CP_BULK(smem_base + 49152, (const char*)(d_gb_lo + ((size_t)b * NDIM + j0) * KDIM),
                16384, MB);
    }
    if (PASS == 2 && tid < 128)
        sZ[tid] = 1.0f / d_Z[b * NDIM + j0 + tid];
    __syncthreads();
    mbar_wait_parity(MB, 0);

    float acc[4][4][4];
    #pragma unroll
    for (int mf = 0; mf < 4; mf++)
        #pragma unroll
        for (int nf = 0; nf < 4; nf++)
            #pragma unroll
            for (int e = 0; e < 4; e++) acc[mf][nf][e] = 0.f;

    uint32_t tA = smem_base, tAlo = smem_base + 16384;
    uint32_t tB = smem_base + 32768, tBlo = smem_base + 49152;
    #pragma unroll
    for (int ks = 0; ks < 4; ks++) {
        int kc = ks * 2;
        uint32_t ahi[4][4], alo[4][4], bhi[4][2], blo[4][2];
        #pragma unroll
        for (int mf = 0; mf < 4; mf++) ldA(tA, wm * 64 + mf * 16, kc, lane, ahi[mf]);
        ldB4(tB, wn * 32,      kc, lane, &bhi[0][0]);
        ldB4(tB, wn * 32 + 16, kc, lane, &bhi[2][0]);
        #pragma unroll
        for (int mf = 0; mf < 4; mf++)
            #pragma unroll
            for (int nf = 0; nf < 4; nf++) mma_bf16(acc[mf][nf], ahi[mf], bhi[nf]);
        #pragma unroll
        for (int mf = 0; mf < 4; mf++) ldA(tAlo, wm * 64 + mf * 16, kc, lane, alo[mf]);
        #pragma unroll
        for (int mf = 0; mf < 4; mf++)
            #pragma unroll
            for (int nf = 0; nf < 4; nf++) mma_bf16(acc[mf][nf], alo[mf], bhi[nf]);
        ldB4(tBlo, wn * 32,      kc, lane, &blo[0][0]);
        ldB4(tBlo, wn * 32 + 16, kc, lane, &blo[2][0]);
        #pragma unroll
        for (int mf = 0; mf < 4; mf++)
            #pragma unroll
            for (int nf = 0; nf < 4; nf++) mma_bf16(acc[mf][nf], ahi[mf], blo[nf]);
    }

    // -------- register-resident epilogue --------
    if (PASS == 1) {
        #pragma unroll
        for (int nf = 0; nf < 4; nf++) {
            float s0 = 0.f, s1 = 0.f;
            #pragma unroll
            for (int mf = 0; mf < 4; mf++) {
                s0 += fast_exp2(acc[mf][nf][0]) + fast_exp2(acc[mf][nf][2]);
                s1 += fast_exp2(acc[mf][nf][1]) + fast_exp2(acc[mf][nf][3]);
            }
            #pragma unroll
            for (int o = 4; o < 32; o <<= 1) {
                s0 += __shfl_xor_sync(0xFFFFFFFFu, s0, o);
                s1 += __shfl_xor_sync(0xFFFFFFFFu, s1, o);
            }
            if (lane < 4) {
                int cc = wn * 32 + nf * 8 + lane * 2;
                atomicAdd(&d_Z[b * NDIM + j0 + cc], s0);
                atomicAdd(&d_Z[b * NDIM + j0 + cc + 1], s1);
            }
        }
    } else {
        // hoist invZ (8 LDS instead of 32)
        float iz[4][2];
        #pragma unroll
        for (int nf = 0; nf < 4; nf++) {
            int cc = wn * 32 + nf * 8 + (lane & 3) * 2;
            iz[nf][0] = sZ[cc];
            iz[nf][1] = sZ[cc + 1];
        }
        float rs0[4], rs1[4];
        #pragma unroll
        for (int mf = 0; mf < 4; mf++) { rs0[mf] = 0.f; rs1[mf] = 0.f; }
        float* ob = beta_out + (size_t)b * NN;
        bool even = (lane & 1) == 0;
        #pragma unroll
        for (int mf = 0; mf < 4; mf++) {
            int r = wm * 64 + mf * 16 + (lane >> 2);
            #pragma unroll
            for (int nf = 0; nf < 4; nf++) {
                float v0 = fast_exp2(acc[mf][nf][0]) * iz[nf][0];
                float v1 = fast_exp2(acc[mf][nf][1]) * iz[nf][1];
                float v2 = fast_exp2(acc[mf][nf][2]) * iz[nf][0];
                float v3 = fast_exp2(acc[mf][nf][3]) * iz[nf][1];
                rs0[mf] += v0 + v1;
                rs1[mf] += v2 + v3;
                // lane-pair exchange: partner lane^1 owns cols cc^2-side pair
                float pv0 = __shfl_xor_sync(0xFFFFFFFFu, v0, 1);
                float pv1 = __shfl_xor_sync(0xFFFFFFFFu, v1, 1);
                float pv2 = __shfl_xor_sync(0xFFFFFFFFu, v2, 1);
                float pv3 = __shfl_xor_sync(0xFFFFFFFFu, v3, 1);
                int cc = wn * 32 + nf * 8 + (lane & 3) * 2;
                if (even) {
                    // row r: my cols cc,cc+1 then partner's cc+2,cc+3
                    __stcs((float4*)(ob + (size_t)(i0 + r) * NDIM + j0 + cc),
                           make_float4(v0, v1, pv0, pv1));
                } else {
                    // row r+8: partner's cols cc-2,cc-1 then mine cc,cc+1
                    __stcs((float4*)(ob + (size_t)(i0 + r + 8) * NDIM + j0 + cc - 2),
                           make_float4(pv2, pv3, v2, v3));
                }
            }
        }
        #pragma unroll
        for (int mf = 0; mf < 4; mf++) {
            #pragma unroll
            for (int o = 1; o < 4; o <<= 1) {
                rs0[mf] += __shfl_xor_sync(0xFFFFFFFFu, rs0[mf], o);
                rs1[mf] += __shfl_xor_sync(0xFFFFFFFFu, rs1[mf], o);
            }
        }
        if ((lane & 3) == 0) {
            #pragma unroll
            for (int mf = 0; mf < 4; mf++) {
                int r = wm * 64 + mf * 16 + (lane >> 2);
                atomicAdd(&d_rowsum[b * NDIM + i0 + r], rs0[mf]);
                atomicAdd(&d_rowsum[b * NDIM + i0 + r + 8], rs1[mf]);
            }
        }
    }
}

// ---------------- pooled epilogue ----------------
// grid (CDIM, BATCH), 128 threads: 4 warps per channel, each N/4, smem combine.
__global__ __launch_bounds__(128) void pool1_kernel(const float* __restrict__ x) {
    __shared__ float pay[4], pax[4];
    int b = blockIdx.y;
    int cc = blockIdx.x;
    int tid = threadIdx.x;
    int lane = tid & 31, wid = tid >> 5;
    const float4* xr = (const float4*)(x + ((size_t)b * CDIM + cc) * NDIM);
    const float4* rs = (const float4*)(d_rowsum + b * NDIM);
    int base = wid * 256 + lane;   // this warp covers float4 indices [wid*256, +256)
    float ay = 0.f, ax = 0.f;
    #pragma unroll
    for (int q = 0; q < 8; q++) {
        float4 xv = xr[base + q * 32];
        float4 rv = rs[base + q * 32];
        ay += xv.x * rv.x + xv.y * rv.y + xv.z * rv.z + xv.w * rv.w;
        ax += xv.x + xv.y + xv.z + xv.w;
    }
    ay = warp_sum(ay); ax = warp_sum(ax);
    if (lane == 0) { pay[wid] = ay; pax[wid] = ax; }
    __syncthreads();
    if (tid == 0) {
        d_y[b * CDIM + cc]    = (pay[0] + pay[1] + pay[2] + pay[3]) * (1.0f / NDIM);
        d_xbar[b * CDIM + cc] = (pax[0] + pax[1] + pax[2] + pax[3]) * (1.0f / NDIM);
    }
}

__global__ __launch_bounds__(256) void pool2_kernel(const float* __restrict__ Wv,
                                                    const float* __restrict__ gamma,
                                                    float* __restrict__ out) {
    int b = blockIdx.y;
    int c = blockIdx.x * 8 + (threadIdx.x >> 5);
    int lane = threadIdx.x & 31;
    const float* wr = Wv + (size_t)c * CDIM;
    const float* yb = d_y + b * CDIM;
    float a = 0.f;
    for (int k = lane; k < CDIM; k += 32) a += wr[k] * yb[k];
    a = warp_sum(a);
    if (lane == 0) out[b * CDIM + c] = gamma[0] * a + d_xbar[b * CDIM + c];
}

// ---------------- launch ----------------
extern "C" void kernel_launch(void* const* d_in, const int* in_sizes, int n_in,
                              void* d_out, int out_size) {
    const float* x     = (const float*)d_in[0];
    const float* Wq    = (const float*)d_in[1];
    const float* Wk    = (const float*)d_in[2];
    const float* Wv    = (const float*)d_in[3];
    const float* gamma = (const float*)d_in[4];
    float* out    = (float*)d_out;
    float* pooled = out;                 // [B,C,1,1] = 2048 floats
    float* beta   = out + BATCH * CDIM;  // [B,N,N]

    cudaFuncSetAttribute(fg_kernel, cudaFuncAttributeMaxDynamicSharedMemorySize, FG_SMEM);
    cudaFuncSetAttribute(attn_kernel<1>, cudaFuncAttributeMaxDynamicSharedMemorySize,
                         ATTN_SMEM);
    cudaFuncSetAttribute(attn_kernel<2>, cudaFuncAttributeMaxDynamicSharedMemorySize,
                         ATTN_SMEM);

    wsplit_kernel<<<(128 * CDIM + 255) / 256, 256>>>(Wq, Wk);
    fg_kernel<<<dim3(64, BATCH), 256, FG_SMEM>>>(x);
    attn_kernel<1><<<dim3(32, 32, BATCH), 256, ATTN_SMEM>>>(beta);
    attn_kernel<2><<<dim3(32, 32, BATCH), 256, ATTN_SMEM>>>(beta);
    pool1_kernel<<<dim3(CDIM, BATCH), 128>>>(x);
    pool2_kernel<<<dim3(CDIM / 8, BATCH), 256>>>(Wv, gamma, pooled);
}

// round 17
// speedup vs baseline: 1.0467x; 1.0467x over previous
#include <cuda_runtime.h>
#include <cuda_bf16.h>
#include <cstdint>
#include <cstddef>

#define BATCH 4
#define CDIM  512
#define KDIM  64
#define NDIM  4096
#define NN    ((size_t)NDIM * NDIM)

// ---------------- device scratch (no allocs allowed) ----------------
// f/g operand arrays are stored PRE-SWIZZLED (XOR-16B within each
// 128-row x 64-col tile; pattern depends only on row&7) so attention can
// bulk-copy them linearly.  f is additionally pre-scaled by log2(e).
// d_w_* are stored pre-swizzled in CHUNK-MAJOR tile order: chunk c (k-range
// 64c..64c+63) occupies elements [c*8192, (c+1)*8192) as a [128m][64k]
// XOR-swizzled tile, so fg can bulk-copy 16KB per chunk linearly.
__device__ __align__(128) __nv_bfloat16 d_fa_hi[BATCH * NDIM * KDIM]; // f, i-major
__device__ __align__(128) __nv_bfloat16 d_fa_lo[BATCH * NDIM * KDIM];
__device__ __align__(128) __nv_bfloat16 d_gb_hi[BATCH * NDIM * KDIM]; // g, j-major
__device__ __align__(128) __nv_bfloat16 d_gb_lo[BATCH * NDIM * KDIM];
__device__ __align__(128) __nv_bfloat16 d_w_hi[128 * CDIM];           // [Wq*L2E;Wk] split
__device__ __align__(128) __nv_bfloat16 d_w_lo[128 * CDIM];
__device__ float d_Z[BATCH * NDIM];       // column sums of 2^s'
__device__ float d_rowsum[BATCH * NDIM];  // row sums of beta
__device__ float d_y[BATCH * CDIM];
__device__ float d_xbar[BATCH * CDIM];

// 2^x  (operands pre-scaled by log2 e upstream)
__device__ __forceinline__ float fast_exp2(float x) {
    float y;
    asm("ex2.approx.ftz.f32 %0, %1;" : "=f"(y) : "f"(x));
    return y;
}

__device__ __forceinline__ float warp_sum(float v) {
    #pragma unroll
    for (int o = 16; o; o >>= 1) v += __shfl_xor_sync(0xFFFFFFFFu, v, o);
    return v;
}

__device__ __forceinline__ uint32_t smem_u32(const void* p) {
    uint32_t a;
    asm("{ .reg .u64 t; cvta.to.shared.u64 t, %1; cvt.u32.u64 %0, t; }"
        : "=r"(a) : "l"(p));
    return a;
}

// hi bf16x2 of (v0,v1) by mantissa truncation (exact bf16 bits)
__device__ __forceinline__ uint32_t pack_hi2(float v0, float v1) {
    uint32_t r;
    asm("prmt.b32 %0, %1, %2, 0x7632;"
        : "=r"(r) : "r"(__float_as_uint(v0)), "r"(__float_as_uint(v1)));
    return r;
}
// residual lo bf16x2: lo_k = v_k - trunc_bf16(v_k), rounded to bf16
__device__ __forceinline__ uint32_t pack_lo2(float v0, float v1) {
    float l0 = v0 - __uint_as_float(__float_as_uint(v0) & 0xFFFF0000u);
    float l1 = v1 - __uint_as_float(__float_as_uint(v1) & 0xFFFF0000u);
    uint32_t r;
    asm("cvt.rn.bf16x2.f32 %0, %1, %2;" : "=r"(r) : "f"(l1), "f"(l0));
    return r;
}

// A fragment (m16 x k16) via ldmatrix x4 from m-major SW-swizzled [rows][64] bf16 tile
__device__ __forceinline__ void ldA(uint32_t tile, int rbase, int kc, int lane, uint32_t* a) {
    int r = rbase + (lane & 15);
    int c = kc + (lane >> 4);
    uint32_t addr = tile + r * 128 + ((c ^ (r & 7)) << 4);
    asm volatile("ldmatrix.sync.aligned.m8n8.x4.shared.b16 {%0,%1,%2,%3}, [%4];"
                 : "=r"(a[0]), "=r"(a[1]), "=r"(a[2]), "=r"(a[3]) : "r"(addr));
}

// TWO B fragments (two adjacent n8 x k16) via one ldmatrix x4
__device__ __forceinline__ void ldB4(uint32_t tile, int rbase, int kc, int lane, uint32_t* b01) {
    int r = rbase + ((lane >> 1) & 8) + (lane & 7);
    int c = kc + ((lane >> 3) & 1);
    uint32_t addr = tile + r * 128 + ((c ^ (r & 7)) << 4);
    asm volatile("ldmatrix.sync.aligned.m8n8.x4.shared.b16 {%0,%1,%2,%3}, [%4];"
                 : "=r"(b01[0]), "=r"(b01[1]), "=r"(b01[2]), "=r"(b01[3]) : "r"(addr));
}

__device__ __forceinline__ void mma_bf16(float* acc, const uint32_t* a, const uint32_t* bb) {
    asm volatile(
        "mma.sync.aligned.m16n8k16.row.col.f32.bf16.bf16.f32 "
        "{%0,%1,%2,%3}, {%4,%5,%6,%7}, {%8,%9}, {%0,%1,%2,%3};"
        : "+f"(acc[0]), "+f"(acc[1]), "+f"(acc[2]), "+f"(acc[3])
        : "r"(a[0]), "r"(a[1]), "r"(a[2]), "r"(a[3]), "r"(bb[0]), "r"(bb[1]));
}

// ---------------- mbarrier + bulk-copy helpers (sm_90 baseline PTX) ----------------
#define MBARRIER_INIT(mbar, count) \
    asm volatile("mbarrier.init.shared.b64 [%0], %1;" \
                 :: "r"((uint32_t)(mbar)), "r"((uint32_t)(count)) : "memory")
#define MBARRIER_EXPECT_TX(mbar, bytes) \
    asm volatile("mbarrier.arrive.expect_tx.shared.b64 _, [%0], %1;" \
                 :: "r"((uint32_t)(mbar)), "r"((uint32_t)(bytes)) : "memory")
#define FENCE_PROXY_ASYNC() \
    asm volatile("fence.proxy.async.shared::cta;" ::: "memory")
#define CP_BULK(dst_smem, src_gmem, bytes, mbar) \
    asm volatile("cp.async.bulk.shared::cta.global.mbarrier::complete_tx::bytes " \
                 "[%0], [%1], %2, [%3];" \
                 :: "r"((uint32_t)(dst_smem)), "l"(src_gmem), "r"((uint32_t)(bytes)), \
                    "r"((uint32_t)(mbar)) : "memory")

__device__ __forceinline__ void mbar_wait_parity(uint32_t mbar, uint32_t parity) {
    uint32_t done;
    asm volatile(
        "{\n\t.reg .pred p;\n\t"
        "mbarrier.try_wait.parity.acquire.cta.shared::cta.b64 p, [%1], %2;\n\t"
        "selp.b32 %0, 1, 0, p;\n\t}"
        : "=r"(done) : "r"(mbar), "r"(parity) : "memory");
    if (!done) {
        asm volatile(
            "{\n\t.reg .pred P1;\n\t"
            "WAIT_LOOP_%=:\n\t"
            "mbarrier.try_wait.parity.acquire.cta.shared::cta.b64 P1, [%0], %1, 0x989680;\n\t"
            "@P1 bra.uni WAIT_DONE_%=;\n\t"
            "bra.uni WAIT_LOOP_%=;\n\t"
            "WAIT_DONE_%=:\n\t}"
            :: "r"(mbar), "r"(parity) : "memory");
    }
}

// ---------------- W split prep + Z/rowsum zero ----------------
// Wq rows pre-scaled by log2(e).  Output PRE-SWIZZLED, CHUNK-MAJOR (see above).
__global__ __launch_bounds__(256) void wsplit_kernel(const float* __restrict__ Wq,
                                                     const float* __restrict__ Wk) {
    int idx = blockIdx.x * blockDim.x + threadIdx.x;
    if (idx < BATCH * NDIM) { d_rowsum[idx] = 0.f; d_Z[idx] = 0.f; }
    if (idx >= 128 * CDIM) return;
    int m = idx >> 9;
    int c = idx & 511;
    float w = (m < 64) ? Wq[m * CDIM + c] * 1.4426950408889634f
                       : Wk[(m - 64) * CDIM + c];
    __nv_bfloat16 hi = __float2bfloat16(w);
    int chunk = c >> 6, kin = c & 63, oct = kin >> 3, e = kin & 7;
    int off = chunk * 8192 + m * 64 + ((oct ^ (m & 7)) << 3) + e;
    d_w_hi[off] = hi;
    d_w_lo[off] = __float2bfloat16(w - __bfloat162float(hi));
}

// ---------------- FG: [f;g] = [Wq*L2E;Wk] @ x[b] via bf16x3 mma.sync ----------------
// Tile: [128 m] x [64 n=i], K=512 in 8 chunks of 64.  grid (64, BATCH), 2 CTAs/SM.
// W chunks stream via 2-stage cp.async.bulk ring (pre-swizzled chunk tiles);
// x chunk prefetched into registers during the previous chunk's MMA.
// SMEM: W ring 2 x 32K @0; sXhi @65536 8K; sXlo @73728 8K; mbars @81920.
#define FG_SMEM 82048

__global__ __launch_bounds__(256, 2) void fg_kernel(const float* __restrict__ x) {
    extern __shared__ __align__(1024) char dynsm[];
    uint32_t smem_base = smem_u32(dynsm);
    uint4* sXhi = (uint4*)(dynsm + 65536);
    uint4* sXlo = (uint4*)(dynsm + 73728);
    float* S = (float*)dynsm;  // [128][68] alias after mainloop
    const uint32_t MBF0 = smem_base + 81920;
    const uint32_t MBF1 = smem_base + 81928;
    const char* wh = (const char*)d_w_hi;
    const char* wl = (const char*)d_w_lo;

    int b = blockIdx.y;
    int i0 = blockIdx.x * 64;
    int tid = threadIdx.x;
    int lane = tid & 31, wid = tid >> 5;
    int wm = wid >> 1, wn = wid & 1;
    const float* xb = x + (size_t)b * CDIM * NDIM;

    int xn[2], xoct[2];
    #pragma unroll
    for (int t = 0; t < 2; t++) {
        int idx = tid + t * 256;
        xn[t] = idx & 63;
        xoct[t] = idx >> 6;
    }

    float acc[2][4][4];
    #pragma unroll
    for (int mf = 0; mf < 2; mf++)
        #pragma unroll
        for (int nf = 0; nf < 4; nf++)
            #pragma unroll
            for (int e = 0; e < 4; e++) acc[mf][nf][e] = 0.f;

    // prologue: init ring, kick off W chunk 0, prefetch x chunk 0 regs
    if (tid == 0) {
        MBARRIER_INIT(MBF0, 1);
        MBARRIER_INIT(MBF1, 1);
        FENCE_PROXY_ASYNC();
        MBARRIER_EXPECT_TX(MBF0, 32768);
        CP_BULK(smem_base,         wh, 16384, MBF0);
        CP_BULK(smem_base + 16384, wl, 16384, MBF0);
    }
    float vreg[2][8];
    #pragma unroll
    for (int t = 0; t < 2; t++) {
        const float* src = xb + (size_t)(xoct[t] * 8) * NDIM + i0 + xn[t];
        #pragma unroll
        for (int j = 0; j < 8; j++) vreg[t][j] = src[(size_t)j * NDIM];
    }
    __syncthreads();  // mbar init visible before any wait

    for (int it = 0; it < 8; it++) {
        // barrier: prev iteration's MMA done with sX and with stage ((it+1)&1)
        __syncthreads();

        // issue W copy for chunk it+1 into stage (it+1)&1 (freed by chunk it-1)
        if (tid == 0 && it + 1 < 8) {
            int ns = (it + 1) & 1;
            uint32_t mb = ns ? MBF1 : MBF0;
            uint32_t st = smem_base + ns * 32768;
            MBARRIER_EXPECT_TX(mb, 32768);
            CP_BULK(st,         wh + (size_t)(it + 1) * 16384, 16384, mb);
            CP_BULK(st + 16384, wl + (size_t)(it + 1) * 16384, 16384, mb);
        }

        // store prefetched x regs -> smem (convert to split bf16)
        #pragma unroll
        for (int t = 0; t < 2; t++) {
            uint4 hw, lw;
            hw.x = pack_hi2(vreg[t][0], vreg[t][1]); lw.x = pack_lo2(vreg[t][0], vreg[t][1]);
            hw.y = pack_hi2(vreg[t][2], vreg[t][3]); lw.y = pack_lo2(vreg[t][2], vreg[t][3]);
            hw.z = pack_hi2(vreg[t][4], vreg[t][5]); lw.z = pack_lo2(vreg[t][4], vreg[t][5]);
            hw.w = pack_hi2(vreg[t][6], vreg[t][7]); lw.w = pack_lo2(vreg[t][6], vreg[t][7]);
            int soff = xn[t] * 8 + (xoct[t] ^ (xn[t] & 7));
            sXhi[soff] = hw;
            sXlo[soff] = lw;
        }
        __syncthreads();  // sX visible to all warps

        // prefetch next x chunk; latency hides under the MMA loop
        if (it < 7) {
            #pragma unroll
            for (int t = 0; t < 2; t++) {
                const float* src = xb + (size_t)((it + 1) * 64 + xoct[t] * 8) * NDIM
                                   + i0 + xn[t];
                #pragma unroll
                for (int j = 0; j < 8; j++) vreg[t][j] = src[(size_t)j * NDIM];
            }
        }

        // wait for this chunk's W tiles
        int s = it & 1;
        mbar_wait_parity(s ? MBF1 : MBF0, (it >> 1) & 1);

        uint32_t tA = smem_base + s * 32768, tAlo = tA + 16384;
        uint32_t tB = smem_base + 65536, tBlo = smem_base + 73728;
        #pragma unroll
        for (int ks = 0; ks < 4; ks++) {
            int kc = ks * 2;
            uint32_t ahi[2][4], alo[2][4], bhi[4][2], blo[4][2];
            #pragma unroll
            for (int mf = 0; mf < 2; mf++) ldA(tA, wm * 32 + mf * 16, kc, lane, ahi[mf]);
            ldB4(tB, wn * 32,      kc, lane, &bhi[0][0]);
            ldB4(tB, wn * 32 + 16, kc, lane, &bhi[2][0]);
            #pragma unroll
            for (int mf = 0; mf < 2; mf++)
                #pragma unroll
                for (int nf = 0; nf < 4; nf++) mma_bf16(acc[mf][nf], ahi[mf], bhi[nf]);
            #pragma unroll
            for (int mf = 0; mf < 2; mf++) ldA(tAlo, wm * 32 + mf * 16, kc, lane, alo[mf]);
            #pragma unroll
            for (int mf = 0; mf < 2; mf++)
                #pragma unroll
                for (int nf = 0; nf < 4; nf++) mma_bf16(acc[mf][nf], alo[mf], bhi[nf]);
            ldB4(tBlo, wn * 32,      kc, lane, &blo[0][0]);
            ldB4(tBlo, wn * 32 + 16, kc, lane, &blo[2][0]);
            #pragma unroll
            for (int mf = 0; mf < 2; mf++)
                #pragma unroll
                for (int nf = 0; nf < 4; nf++) mma_bf16(acc[mf][nf], ahi[mf], blo[nf]);
        }
    }
    __syncthreads();

    // stage fp32 S[m][i] (128 x 64, stride 68)
    #pragma unroll
    for (int mf = 0; mf < 2; mf++)
        #pragma unroll
        for (int nf = 0; nf < 4; nf++) {
            int r = wm * 32 + mf * 16 + (lane >> 2);
            int cc = wn * 32 + nf * 8 + (lane & 3) * 2;
            S[r * 68 + cc]           = acc[mf][nf][0];
            S[r * 68 + cc + 1]       = acc[mf][nf][1];
            S[(r + 8) * 68 + cc]     = acc[mf][nf][2];
            S[(r + 8) * 68 + cc + 1] = acc[mf][nf][3];
        }
    __syncthreads();

    // write split bf16 PRE-SWIZZLED: chunk index XORed with (row & 7)
    int arr = lane >> 3, chunk = lane & 7;
    int mbase = (arr >= 2 ? 64 : 0) + chunk * 8;
    __nv_bfloat16* dst = (arr == 0) ? d_fa_hi : (arr == 1) ? d_fa_lo
                       : (arr == 2) ? d_gb_hi : d_gb_lo;
    bool lo_arr = (arr & 1);
    for (int r = wid; r < 64; r += 8) {
        uint4 wv;
        float v0, v1;
        v0 = S[(mbase + 0) * 68 + r]; v1 = S[(mbase + 1) * 68 + r];
        wv.x = lo_arr ? pack_lo2(v0, v1) : pack_hi2(v0, v1);
        v0 = S[(mbase + 2) * 68 + r]; v1 = S[(mbase + 3) * 68 + r];
        wv.y = lo_arr ? pack_lo2(v0, v1) : pack_hi2(v0, v1);
        v0 = S[(mbase + 4) * 68 + r]; v1 = S[(mbase + 5) * 68 + r];
        wv.z = lo_arr ? pack_lo2(v0, v1) : pack_hi2(v0, v1);
        v0 = S[(mbase + 6) * 68 + r]; v1 = S[(mbase + 7) * 68 + r];
        wv.w = lo_arr ? pack_lo2(v0, v1) : pack_hi2(v0, v1);
        int chs = chunk ^ (r & 7);
        *(uint4*)(dst + ((size_t)b * NDIM + i0 + r) * KDIM + chs * 8) = wv;
    }
}

// ---------------- attention passes (split, fine-grained grids) ----------------
// grid (32,32,BATCH) = (jtile, itile, b); tile 128(i) x 128(j); 256 threads.
// Operands loaded via 4 bulk copies (arrays pre-swizzled).  Register epilogues.
// PASS 1: Z[b,j] += sum_i 2^s.  PASS 2: beta = 2^s/Z, rowsum += sum_j beta.
// SMEM: [0,64K) 4 operand tiles; sZ @65536 (512B); mbar @66048.
#define ATTN_SMEM 66176

template <int PASS>
__global__ __launch_bounds__(256, 2) void attn_kernel(float* __restrict__ beta_out) {
    extern __shared__ __align__(1024) char dynsm[];
    uint32_t smem_base = smem_u32(dynsm);
    float* sZ = (float*)(dynsm + 65536);
    const uint32_t MB = smem_base + 66048;

    int b  = blockIdx.z;
    int i0 = blockIdx.y * 128;
    int j0 = blockIdx.x * 128;
    int tid = threadIdx.x;
    int lane = tid & 31, wid = tid >> 5;
    int wm = wid >> 2, wn = wid & 3;

    if (tid == 0) {
        MBARRIER_INIT(MB, 1);
        FENCE_PROXY_ASYNC();
        MBARRIER_EXPECT_TX(MB, 65536);
        CP_BULK(smem_base,         (const char*)(d_fa_hi + ((size_t)b * NDIM + i0) * KDIM),
                16384, MB);
        CP_BULK(smem_base + 16384, (const char*)(d_fa_lo + ((size_t)b * NDIM + i0) * KDIM),
                16384, MB);
        CP_BULK(smem_base + 32768, (const char*)(d_gb_hi + ((size_t)b * NDIM + j0) * KDIM),
                16384, MB);
        CP_BULK(smem_base + 49152, (const char*)(d_gb_lo + ((size_t)b * NDIM + j0) * KDIM),
                16384, MB);
    }
    if (PASS == 2 && tid < 128)
        sZ[tid] = 1.0f / d_Z[b * NDIM + j0 + tid];
    __syncthreads();
    mbar_wait_parity(MB, 0);

    float acc[4][4][4];
    #pragma unroll
    for (int mf = 0; mf < 4; mf++)
        #pragma unroll
        for (int nf = 0; nf < 4; nf++)
            #pragma unroll
            for (int e = 0; e < 4; e++) acc[mf][nf][e] = 0.f;

    uint32_t tA = smem_base, tAlo = smem_base + 16384;
    uint32_t tB = smem_base + 32768, tBlo = smem_base + 49152;
    #pragma unroll
    for (int ks = 0; ks < 4; ks++) {
        int kc = ks * 2;
        uint32_t ahi[4][4], alo[4][4], bhi[4][2], blo[4][2];
        #pragma unroll
        for (int mf = 0; mf < 4; mf++) ldA(tA, wm * 64 + mf * 16, kc, lane, ahi[mf]);
        ldB4(tB, wn * 32,      kc, lane, &bhi[0][0]);
        ldB4(tB, wn * 32 + 16, kc, lane, &bhi[2][0]);
        #pragma unroll
        for (int mf = 0; mf < 4; mf++)
            #pragma unroll
            for (int nf = 0; nf < 4; nf++) mma_bf16(acc[mf][nf], ahi[mf], bhi[nf]);
        #pragma unroll
        for (int mf = 0; mf < 4; mf++) ldA(tAlo, wm * 64 + mf * 16, kc, lane, alo[mf]);
        #pragma unroll
        for (int mf = 0; mf < 4; mf++)
            #pragma unroll
            for (int nf = 0; nf < 4; nf++) mma_bf16(acc[mf][nf], alo[mf], bhi[nf]);
        ldB4(tBlo, wn * 32,      kc, lane, &blo[0][0]);
        ldB4(tBlo, wn * 32 + 16, kc, lane, &blo[2][0]);
        #pragma unroll
        for (int mf = 0; mf < 4; mf++)
            #pragma unroll
            for (int nf = 0; nf < 4; nf++) mma_bf16(acc[mf][nf], ahi[mf], blo[nf]);
    }

    // -------- register-resident epilogue --------
    if (PASS == 1) {
        #pragma unroll
        for (int nf = 0; nf < 4; nf++) {
            float s0 = 0.f, s1 = 0.f;
            #pragma unroll
            for (int mf = 0; mf < 4; mf++) {
                s0 += fast_exp2(acc[mf][nf][0]) + fast_exp2(acc[mf][nf][2]);
                s1 += fast_exp2(acc[mf][nf][1]) + fast_exp2(acc[mf][nf][3]);
            }
            #pragma unroll
            for (int o = 4; o < 32; o <<= 1) {
                s0 += __shfl_xor_sync(0xFFFFFFFFu, s0, o);
                s1 += __shfl_xor_sync(0xFFFFFFFFu, s1, o);
            }
            if (lane < 4) {
                int cc = wn * 32 + nf * 8 + lane * 2;
                atomicAdd(&d_Z[b * NDIM + j0 + cc], s0);
                atomicAdd(&d_Z[b * NDIM + j0 + cc + 1], s1);
            }
        }
    } else {
        // hoisted invZ (8 LDS instead of 32)
        float iz[4][2];
        #pragma unroll
        for (int nf = 0; nf < 4; nf++) {
            int cc = wn * 32 + nf * 8 + (lane & 3) * 2;
            iz[nf][0] = sZ[cc];
            iz[nf][1] = sZ[cc + 1];
        }
        float rs0[4], rs1[4];
        #pragma unroll
        for (int mf = 0; mf < 4; mf++) { rs0[mf] = 0.f; rs1[mf] = 0.f; }
        float* ob = beta_out + (size_t)b * NN;
        #pragma unroll
        for (int mf = 0; mf < 4; mf++) {
            int r = wm * 64 + mf * 16 + (lane >> 2);
            #pragma unroll
            for (int nf = 0; nf < 4; nf++) {
                int cc = wn * 32 + nf * 8 + (lane & 3) * 2;
                float v0 = fast_exp2(acc[mf][nf][0]) * iz[nf][0];
                float v1 = fast_exp2(acc[mf][nf][1]) * iz[nf][1];
                float v2 = fast_exp2(acc[mf][nf][2]) * iz[nf][0];
                float v3 = fast_exp2(acc[mf][nf][3]) * iz[nf][1];
                __stcs((float2*)(ob + (size_t)(i0 + r) * NDIM + j0 + cc),
                       make_float2(v0, v1));
                __stcs((float2*)(ob + (size_t)(i0 + r + 8) * NDIM + j0 + cc),
                       make_float2(v2, v3));
                rs0[mf] += v0 + v1;
                rs1[mf] += v2 + v3;
            }
        }
        #pragma unroll
        for (int mf = 0; mf < 4; mf++) {
            #pragma unroll
            for (int o = 1; o < 4; o <<= 1) {
                rs0[mf] += __shfl_xor_sync(0xFFFFFFFFu, rs0[mf], o);
                rs1[mf] += __shfl_xor_sync(0xFFFFFFFFu, rs1[mf], o);
            }
        }
        if ((lane & 3) == 0) {
            #pragma unroll
            for (int mf = 0; mf < 4; mf++) {
                int r = wm * 64 + mf * 16 + (lane >> 2);
                atomicAdd(&d_rowsum[b * NDIM + i0 + r], rs0[mf]);
                atomicAdd(&d_rowsum[b * NDIM + i0 + r + 8], rs1[mf]);
            }
        }
    }
}

// ---------------- pooled epilogue ----------------
// grid (CDIM, BATCH), 128 threads: 4 warps per channel, each N/4, smem combine.
__global__ __launch_bounds__(128) void pool1_kernel(const float* __restrict__ x) {
    __shared__ float pay[4], pax[4];
    int b = blockIdx.y;
    int cc = blockIdx.x;
    int tid = threadIdx.x;
    int lane = tid & 31, wid = tid >> 5;
    const float4* xr = (const float4*)(x + ((size_t)b * CDIM + cc) * NDIM);
    const float4* rs = (const float4*)(d_rowsum + b * NDIM);
    int base = wid * 256 + lane;   // this warp covers float4 indices [wid*256, +256)
    float ay = 0.f, ax = 0.f;
    #pragma unroll
    for (int q = 0; q < 8; q++) {
        float4 xv = xr[base + q * 32];
        float4 rv = rs[base + q * 32];
        ay += xv.x * rv.x + xv.y * rv.y + xv.z * rv.z + xv.w * rv.w;
        ax += xv.x + xv.y + xv.z + xv.w;
    }
    ay = warp_sum(ay); ax = warp_sum(ax);
    if (lane == 0) { pay[wid] = ay; pax[wid] = ax; }
    __syncthreads();
    if (tid == 0) {
        d_y[b * CDIM + cc]    = (pay[0] + pay[1] + pay[2] + pay[3]) * (1.0f / NDIM);
        d_xbar[b * CDIM + cc] = (pax[0] + pax[1] + pax[2] + pax[3]) * (1.0f / NDIM);
    }
}

__global__ __launch_bounds__(256) void pool2_kernel(const float* __restrict__ Wv,
                                                    const float* __restrict__ gamma,
                                                    float* __restrict__ out) {
    int b = blockIdx.y;
    int c = blockIdx.x * 8 + (threadIdx.x >> 5);
    int lane = threadIdx.x & 31;
    const float* wr = Wv + (size_t)c * CDIM;
    const float* yb = d_y + b * CDIM;
    float a = 0.f;
    for (int k = lane; k < CDIM; k += 32) a += wr[k] * yb[k];
    a = warp_sum(a);
    if (lane == 0) out[b * CDIM + c] = gamma[0] * a + d_xbar[b * CDIM + c];
}

// ---------------- launch ----------------
extern "C" void kernel_launch(void* const* d_in, const int* in_sizes, int n_in,
                              void* d_out, int out_size) {
    const float* x     = (const float*)d_in[0];
    const float* Wq    = (const float*)d_in[1];
    const float* Wk    = (const float*)d_in[2];
    const float* Wv    = (const float*)d_in[3];
    const float* gamma = (const float*)d_in[4];
    float* out    = (float*)d_out;
    float* pooled = out;                 // [B,C,1,1] = 2048 floats
    float* beta   = out + BATCH * CDIM;  // [B,N,N]

    cudaFuncSetAttribute(fg_kernel, cudaFuncAttributeMaxDynamicSharedMemorySize, FG_SMEM);
    cudaFuncSetAttribute(attn_kernel<1>, cudaFuncAttributeMaxDynamicSharedMemorySize,
                         ATTN_SMEM);
    cudaFuncSetAttribute(attn_kernel<2>, cudaFuncAttributeMaxDynamicSharedMemorySize,
                         ATTN_SMEM);

    wsplit_kernel<<<(128 * CDIM + 255) / 256, 256>>>(Wq, Wk);
    fg_kernel<<<dim3(64, BATCH), 256, FG_SMEM>>>(x);
    attn_kernel<1><<<dim3(32, 32, BATCH), 256, ATTN_SMEM>>>(beta);
    attn_kernel<2><<<dim3(32, 32, BATCH), 256, ATTN_SMEM>>>(beta);
    pool1_kernel<<<dim3(CDIM, BATCH), 128>>>(x);
    pool2_kernel<<<dim3(CDIM / 8, BATCH), 256>>>(Wv, gamma, pooled);
}